// round 11
// baseline (speedup 1.0000x reference)
#include <cuda_runtime.h>
#include <cuda_fp16.h>
#include <cstdint>

// ============================================================================
// out[m,n] = sum_k x[m,k] * (w[k/128, k%128, n] * scaler[k/128, n])
//   x: [2,1024,4096] f32 (M=2048,K=4096)  w: [32,128,4096] INT32  sc: [32,4096]
//
// Model: HMMA.16816.F32 rt~8/SMSP -> GEMM floor 119us. R9/R10 profile: tensor
// 63.7%, L1 52% (=> ~256B/cyc crossbar, smem NOT binding). R11: ks-level +
// cross-iteration fragment double-buffering (ldsm(ks+1) before mma(ks));
// swizzle addressing collapsed to addr0 ^ (ks<<5).
// ============================================================================

static constexpr int M = 2048;
static constexpr int N = 4096;
static constexpr int K = 4096;

static constexpr int BM = 128;
static constexpr int BN = 128;
static constexpr int BK = 64;
static constexpr int STAGES = 3;
static constexpr int KITERS = K / BK;    // 64

static constexpr int A_BYTES = BM * BK * 2;              // 16384
static constexpr int B_BYTES = BN * BK * 2;              // 16384
static constexpr int STAGE_BYTES = A_BYTES + B_BYTES;    // 32768
static constexpr int SMEM_TOTAL = STAGES * STAGE_BYTES;  // 98304 (x2 CTAs/SM)

__device__ __half g_x16[(size_t)M * K];   // 16 MB
__device__ __half g_wt [(size_t)N * K];   // 32 MB

// ---------------------------------------------------------------------------
__device__ __forceinline__ uint32_t smem_u32(const void* p) {
    uint32_t a;
    asm("{ .reg .u64 t; cvta.to.shared.u64 t, %1; cvt.u32.u64 %0, t; }"
        : "=r"(a) : "l"(p));
    return a;
}
__device__ __forceinline__ void cp_async_16(uint32_t dst, const void* src) {
    asm volatile("cp.async.cg.shared.global [%0], [%1], 16;"
                 :: "r"(dst), "l"(src) : "memory");
}
__device__ __forceinline__ void cp_commit() {
    asm volatile("cp.async.commit_group;" ::: "memory");
}
__device__ __forceinline__ void cp_wait1() {
    asm volatile("cp.async.wait_group 1;" ::: "memory");
}
__device__ __forceinline__ void ldsm_x4(uint32_t* r, uint32_t addr) {
    asm volatile("ldmatrix.sync.aligned.m8n8.x4.shared.b16 {%0,%1,%2,%3}, [%4];"
                 : "=r"(r[0]), "=r"(r[1]), "=r"(r[2]), "=r"(r[3]) : "r"(addr));
}
__device__ __forceinline__ void mma16816(float* c, const uint32_t* a,
                                         uint32_t b0, uint32_t b1) {
    asm volatile(
        "mma.sync.aligned.m16n8k16.row.col.f32.f16.f16.f32 "
        "{%0,%1,%2,%3}, {%4,%5,%6,%7}, {%8,%9}, {%0,%1,%2,%3};"
        : "+f"(c[0]), "+f"(c[1]), "+f"(c[2]), "+f"(c[3])
        : "r"(a[0]), "r"(a[1]), "r"(a[2]), "r"(a[3]), "r"(b0), "r"(b1));
}

// ============================================================================
// Kernel 1: merged prepass  [verified R10]
// ============================================================================
static constexpr int DQ_BLOCKS = 2048;
__global__ void __launch_bounds__(256) prep_kernel(const float4* __restrict__ x,
                                                   uint4* __restrict__ xo,
                                                   const int* __restrict__ w,
                                                   const float* __restrict__ sc,
                                                   __half* __restrict__ wt) {
    __shared__ __half tile[128][66];
    const int bid = blockIdx.x;
    const int tid = threadIdx.x;

    if (bid >= DQ_BLOCKS) {
        size_t i = (size_t)(bid - DQ_BLOCKS) * 256 + tid;
        float4 a = x[2 * i];
        float4 b = x[2 * i + 1];
        __half2 h0 = __floats2half2_rn(a.x, a.y);
        __half2 h1 = __floats2half2_rn(a.z, a.w);
        __half2 h2 = __floats2half2_rn(b.x, b.y);
        __half2 h3 = __floats2half2_rn(b.z, b.w);
        uint4 v;
        v.x = reinterpret_cast<uint32_t&>(h0);
        v.y = reinterpret_cast<uint32_t&>(h1);
        v.z = reinterpret_cast<uint32_t&>(h2);
        v.w = reinterpret_cast<uint32_t&>(h3);
        xo[i] = v;
        return;
    }

    const int s  = bid >> 6;
    const int n0 = (bid & 63) * 64;

    #pragma unroll
    for (int i = tid; i < 128 * 16; i += 256) {
        int c = i >> 4;
        int n = (i & 15) * 4;
        const int4   q = *(const int4*)(w + ((size_t)(s * 128 + c)) * 4096 + n0 + n);
        const float4 f = *(const float4*)(sc + (size_t)s * 4096 + n0 + n);
        __half2 h0 = __floats2half2_rn((float)q.x * f.x, (float)q.y * f.y);
        __half2 h1 = __floats2half2_rn((float)q.z * f.z, (float)q.w * f.w);
        *(__half2*)&tile[c][n]     = h0;
        *(__half2*)&tile[c][n + 2] = h1;
    }
    __syncthreads();

    #pragma unroll
    for (int i = tid; i < 64 * 32; i += 256) {
        int cq = i & 31;
        int n  = i >> 5;
        int c0 = cq * 4;
        uint32_t lo = (uint32_t)__half_as_ushort(tile[c0 + 0][n]) |
                      ((uint32_t)__half_as_ushort(tile[c0 + 1][n]) << 16);
        uint32_t hi = (uint32_t)__half_as_ushort(tile[c0 + 2][n]) |
                      ((uint32_t)__half_as_ushort(tile[c0 + 3][n]) << 16);
        uint2 v; v.x = lo; v.y = hi;
        *(uint2*)(wt + (size_t)(n0 + n) * 4096 + s * 128 + c0) = v;
    }
}

// ============================================================================
// Kernel 2: fp16 HMMA GEMM with fragment double-buffering
//   BM=128 x BN=128 x BK=64, 8 warps (2m x 4n, warp 64m x 32n), 3-stage
//   cp.async ring, 2 CTAs/SM. ldsm(ks+1) issued before mma(ks); ks0 frags of
//   iter it+1 preloaded at iter-it tail (stage it+1 resident by wait_group 1).
// ============================================================================
__global__ void __launch_bounds__(256, 2)
gemm_kernel(const __half* __restrict__ A, const __half* __restrict__ B,
            float* __restrict__ out) {
    extern __shared__ char smem[];
    const uint32_t sb = smem_u32(smem);

    const int tid  = threadIdx.x;
    const int wid  = tid >> 5;
    const int lane = tid & 31;

    const int mt = blockIdx.x & 15;
    const int nt = blockIdx.x >> 4;
    const int m0 = mt * BM;
    const int n0 = nt * BN;

    const int wm = (wid & 1) * 64;
    const int wn = (wid >> 1) * 32;

    // ---- cp.async bases ----
    const int row0 = tid >> 3;
    const int cc   = tid & 7;
    const uint32_t dst0 = (uint32_t)row0 * 128 + (((cc ^ (row0 & 7)) << 4));
    const __half* a_base = A + (size_t)(m0 + row0) * K + cc * 8;
    const __half* b_base = B + (size_t)(n0 + row0) * K + cc * 8;

    // ---- ldsm ks=0 offsets; addr(ks) = (stage_base + off) ^ (ks<<5) ----
    const int a_hi = lane >> 4;
    const int b_hi = (lane >> 3) & 1;
    uint32_t offA[4], offB[2];
    #pragma unroll
    for (int mi = 0; mi < 4; ++mi) {
        int r = wm + mi * 16 + (lane & 15);
        offA[mi] = (uint32_t)r * 128 + (((uint32_t)(a_hi ^ (r & 7))) << 4);
    }
    #pragma unroll
    for (int nb = 0; nb < 2; ++nb) {
        int r = wn + nb * 16 + (lane & 7) + 8 * (lane >> 4);
        offB[nb] = A_BYTES + (uint32_t)r * 128 + (((uint32_t)(b_hi ^ (r & 7))) << 4);
    }

    float acc[4][4][4];
    #pragma unroll
    for (int mi = 0; mi < 4; ++mi)
        #pragma unroll
        for (int ni = 0; ni < 4; ++ni)
            #pragma unroll
            for (int j = 0; j < 4; ++j) acc[mi][ni][j] = 0.f;

    uint32_t af[2][4][4], bf[2][2][4];   // double-buffered fragments

    auto load_stage = [&](int it, int stage) {
        uint32_t sd = sb + stage * STAGE_BYTES;
        size_t koff = (size_t)it * BK;
        #pragma unroll
        for (int i = 0; i < 4; ++i)
            cp_async_16(sd + dst0 + i * (32 * 128), a_base + koff + (size_t)(32 * i) * K);
        #pragma unroll
        for (int i = 0; i < 4; ++i)
            cp_async_16(sd + A_BYTES + dst0 + i * (32 * 128),
                        b_base + koff + (size_t)(32 * i) * K);
    };

    auto ld_frags = [&](uint32_t sbase, int ks, int buf) {
        uint32_t x = (uint32_t)ks << 5;
        #pragma unroll
        for (int mi = 0; mi < 4; ++mi) ldsm_x4(af[buf][mi], (sbase + offA[mi]) ^ x);
        #pragma unroll
        for (int nb = 0; nb < 2; ++nb) ldsm_x4(bf[buf][nb], (sbase + offB[nb]) ^ x);
    };

    // ---- prologue ----
    load_stage(0, 0); cp_commit();
    load_stage(1, 1); cp_commit();
    cp_wait1();                           // stage 0 resident (stage 1 pending)
    __syncthreads();
    load_stage(2, 2); cp_commit();        // pending: {1, 2}
    ld_frags(sb, 0, 0);                   // iter 0, ks 0

    #pragma unroll 1
    for (int it = 0; it < KITERS; ++it) {
        const uint32_t sA = sb + (it % STAGES) * STAGE_BYTES;

        #pragma unroll
        for (int ks = 0; ks < 4; ++ks) {
            if (ks < 3) ld_frags(sA, ks + 1, (ks + 1) & 1);   // prefetch next ks
            const int b = ks & 1;
            #pragma unroll
            for (int mi = 0; mi < 4; ++mi)
                #pragma unroll
                for (int nb = 0; nb < 2; ++nb) {
                    mma16816(acc[mi][2 * nb + 0], af[b][mi], bf[b][nb][0], bf[b][nb][1]);
                    mma16816(acc[mi][2 * nb + 1], af[b][mi], bf[b][nb][2], bf[b][nb][3]);
                }
        }

        // ---- iter tail: confirm stage it+1, recycle slot of stage it ----
        if (it < KITERS - 1) {
            cp_wait1();                   // stage it+1 resident
            __syncthreads();              // all warps done reading stage it
            ld_frags(sb + ((it + 1) % STAGES) * STAGE_BYTES, 0, 0);  // next ks0
            if (it + 3 < KITERS) load_stage(it + 3, (it + 3) % STAGES);
            cp_commit();
        }
    }

    // ---- epilogue (verified c-fragment mapping) ----
    const int r0 = m0 + wm + (lane >> 2);
    const int c0 = n0 + wn + (lane & 3) * 2;
    #pragma unroll
    for (int mi = 0; mi < 4; ++mi) {
        #pragma unroll
        for (int ni = 0; ni < 4; ++ni) {
            int r = r0 + mi * 16;
            int c = c0 + ni * 8;
            *(float2*)(out + (size_t)r * N + c)       = make_float2(acc[mi][ni][0], acc[mi][ni][1]);
            *(float2*)(out + (size_t)(r + 8) * N + c) = make_float2(acc[mi][ni][2], acc[mi][ni][3]);
        }
    }
}

// ============================================================================
// Host launch
// ============================================================================
extern "C" void kernel_launch(void* const* d_in, const int* in_sizes, int n_in,
                              void* d_out, int out_size) {
    const float* x  = (const float*)d_in[0];
    const int*   w  = (const int*)d_in[1];
    const float* sc = (const float*)d_in[2];
    float* out = (float*)d_out;

    void* p_x16 = nullptr;
    void* p_wt  = nullptr;
    cudaGetSymbolAddress(&p_x16, g_x16);
    cudaGetSymbolAddress(&p_wt,  g_wt);

    prep_kernel<<<DQ_BLOCKS + 4096, 256>>>((const float4*)x, (uint4*)p_x16,
                                           w, sc, (__half*)p_wt);

    cudaFuncSetAttribute(gemm_kernel, cudaFuncAttributeMaxDynamicSharedMemorySize,
                         SMEM_TOTAL);
    gemm_kernel<<<(M / BM) * (N / BN), 256, SMEM_TOTAL>>>(
        (const __half*)p_x16, (const __half*)p_wt, out);
}